// round 9
// baseline (speedup 1.0000x reference)
#include <cuda_runtime.h>
#include <cuda_fp16.h>
#include <cstdint>

#define NT 256
#define ROWS 64
#define NCHUNK 16
// smem byte offsets (total 93184 -> 2 CTAs/SM)
#define SM_A    0         // 64 rows x 264 fp16 (stride 528B) = 33792
#define SM_W1   33792     // [hi 32x264 | lo 32x264] = 33792
#define W1LO    16896
#define SM_W2   67584     // [hi 128x40 | lo 128x40] (stride 80B) = 20480
#define W2LO    10240
#define SM_H    88064     // 64 x 40 fp16 (stride 80B) = 5120
#define SM_TOTAL 93184

__device__ float g_agg[50000 * 128];
// weight images: fp16 hi/lo, chunk-contiguous
__device__ __align__(16) __half g_w1m_hi[16 * 32 * 264];
__device__ __align__(16) __half g_w1m_lo[16 * 32 * 264];
__device__ __align__(16) __half g_w2m_hi[16 * 128 * 40];
__device__ __align__(16) __half g_w2m_lo[16 * 128 * 40];
__device__ __align__(16) __half g_w1u_hi[16 * 32 * 264];
__device__ __align__(16) __half g_w1u_lo[16 * 32 * 264];
__device__ __align__(16) __half g_w2u_hi[16 * 128 * 40];
__device__ __align__(16) __half g_w2u_lo[16 * 128 * 40];

__device__ __forceinline__ uint32_t smem_u32(const void* p) {
    uint32_t a;
    asm("{ .reg .u64 t; cvta.to.shared.u64 t, %1; cvt.u32.u64 %0, t; }" : "=r"(a) : "l"(p));
    return a;
}
__device__ __forceinline__ void ldm4(uint32_t addr, uint32_t* r) {
    asm volatile("ldmatrix.sync.aligned.m8n8.x4.shared.b16 {%0,%1,%2,%3}, [%4];"
                 : "=r"(r[0]), "=r"(r[1]), "=r"(r[2]), "=r"(r[3]) : "r"(addr));
}
__device__ __forceinline__ void mma_f16(float* c, const uint32_t* a,
                                        uint32_t b0, uint32_t b1) {
    asm volatile(
        "mma.sync.aligned.m16n8k16.row.col.f32.f16.f16.f32 "
        "{%0,%1,%2,%3}, {%4,%5,%6,%7}, {%8,%9}, {%0,%1,%2,%3};"
        : "+f"(c[0]), "+f"(c[1]), "+f"(c[2]), "+f"(c[3])
        : "r"(a[0]), "r"(a[1]), "r"(a[2]), "r"(a[3]), "r"(b0), "r"(b1));
}
__device__ __forceinline__ void cp16(uint32_t dst, const void* src) {
    asm volatile("cp.async.cg.shared.global [%0], [%1], 16;" :: "r"(dst), "l"(src));
}
__device__ __forceinline__ uint32_t h2bits(__half2 v) {
    return *reinterpret_cast<uint32_t*>(&v);
}

// ---- merged prep: zero agg + 4 weight-image builds, block-range partitioned ----
// zero: blocks [0,6250); w1m [6250,6762); w2m [6762,7018); w1u [7018,7530); w2u [7530,7786)
__global__ void prep_all(const float* __restrict__ W1m, const float* __restrict__ W2m,
                         const float* __restrict__ W1u, const float* __restrict__ W2u,
                         float* __restrict__ agg) {
    int b = blockIdx.x, tid = threadIdx.x;
    if (b < 6250) {
        int i = b * NT + tid;                       // 1.6M float4
        ((float4*)agg)[i] = make_float4(0.f, 0.f, 0.f, 0.f);
        return;
    }
    if (b < 7018) {   // W1 images: [16 chunk(n32)][32 n][264 k]
        const float* W = (b < 6762) ? W1m : W1u;
        __half* hi = (b < 6762) ? g_w1m_hi : g_w1u_hi;
        __half* lo = (b < 6762) ? g_w1m_lo : g_w1u_lo;
        int base = (b < 6762) ? 6250 : 6762;
        // careful: w2m range starts at 6762; w1u at 7018 -- recompute:
        if (b >= 6762) { W = W2m; }                  // placeholder, corrected below
        (void)W;
        int idx = (b - base) * NT + tid;             // 0..131071
        const float* Ws = (b < 6762) ? W1m : W1u;
        if (b >= 6762) { /* unreachable for w1u start fix */ }
        int k = idx >> 9, n = idx & 511;
        float v = Ws[idx];
        __half h = __float2half_rn(v);
        int pos = (n >> 5) * 8448 + (n & 31) * 264 + k;
        hi[pos] = h;
        lo[pos] = __float2half_rn(v - __half2float(h));
        return;
    }
    // unreachable
}

// fixed partition version (the above had overlapping ranges; use this instead)
__global__ void prep_all2(const float* __restrict__ W1m, const float* __restrict__ W2m,
                          const float* __restrict__ W1u, const float* __restrict__ W2u,
                          float* __restrict__ agg) {
    int b = blockIdx.x, tid = threadIdx.x;
    if (b < 6250) {
        ((float4*)agg)[b * NT + tid] = make_float4(0.f, 0.f, 0.f, 0.f);
    } else if (b < 6762 || (b >= 7018 && b < 7530)) {  // W1 images
        bool msg = (b < 6762);
        const float* W = msg ? W1m : W1u;
        __half* hi = msg ? g_w1m_hi : g_w1u_hi;
        __half* lo = msg ? g_w1m_lo : g_w1u_lo;
        int idx = (b - (msg ? 6250 : 7018)) * NT + tid;
        int k = idx >> 9, n = idx & 511;
        float v = W[idx];
        __half h = __float2half_rn(v);
        int pos = (n >> 5) * 8448 + (n & 31) * 264 + k;
        hi[pos] = h;
        lo[pos] = __float2half_rn(v - __half2float(h));
    } else {                                            // W2 images
        bool msg = (b < 7018);
        const float* W = msg ? W2m : W2u;
        __half* hi = msg ? g_w2m_hi : g_w2u_hi;
        __half* lo = msg ? g_w2m_lo : g_w2u_lo;
        int idx = (b - (msg ? 6762 : 7530)) * NT + tid;
        int k = idx >> 7, n = idx & 127;
        float v = W[idx];
        __half h = __float2half_rn(v);
        int pos = (k >> 5) * 5120 + n * 40 + (k & 31);
        hi[pos] = h;
        lo[pos] = __float2half_rn(v - __half2float(h));
    }
}

__device__ __forceinline__ void prefetch_w1(uint32_t sb, int c,
        const __half* w1h, const __half* w1l, int tid) {
    const char* sh = ((const char*)w1h) + c * 16896;
    const char* sl = ((const char*)w1l) + c * 16896;
#pragma unroll
    for (int j = 0; j < 5; ++j) {
        int idx = tid + j * NT;
        if (idx < 1056) {
            cp16(sb + SM_W1 + idx * 16, sh + idx * 16);
            cp16(sb + SM_W1 + W1LO + idx * 16, sl + idx * 16);
        }
    }
}
__device__ __forceinline__ void prefetch_w2(uint32_t sb, int c,
        const __half* w2h, const __half* w2l, int tid) {
    const char* sh = ((const char*)w2h) + c * 10240;
    const char* sl = ((const char*)w2l) + c * 10240;
#pragma unroll
    for (int j = 0; j < 3; ++j) {
        int idx = tid + j * NT;
        if (idx < 640) {
            cp16(sb + SM_W2 + idx * 16, sh + idx * 16);
            cp16(sb + SM_W2 + W2LO + idx * 16, sl + idx * 16);
        }
    }
}

// Fused 2-layer MLP, 64 rows/CTA, 2 CTAs/SM, fp16 A-single / W hi+lo 2-term.
template <bool IS_EDGE>
__global__ __launch_bounds__(NT, 2)
void mlp_mma(const float* __restrict__ x, const float* __restrict__ second,
             const int* __restrict__ eidx,
             const __half* __restrict__ w1h, const __half* __restrict__ w1l,
             const __half* __restrict__ w2h, const __half* __restrict__ w2l,
             const float* __restrict__ b1, const float* __restrict__ b2,
             float* __restrict__ out, int M, int E) {
    extern __shared__ __align__(16) unsigned char smem[];
    const uint32_t sb = smem_u32(smem);
    const int tid = threadIdx.x;
    const int lane = tid & 31;
    const int wid = tid >> 5;
    const int wm = wid & 3, wn = wid >> 2;   // 4 m-warps(16 rows) x 2 n-warps
    const int rowbase = blockIdx.x * ROWS;

    // chunk-0 weights in flight ASAP
    prefetch_w1(sb, 0, w1h, w1l, tid);
    prefetch_w2(sb, 0, w2h, w2l, tid);
    asm volatile("cp.async.commit_group;");

    // ---- gather A = [feat_i(128) | feat_j(128)] -> fp16 smem ----
    {
        int r = tid >> 2, q = tid & 3;
        int half = q >> 1, part = q & 1;
        int row = rowbase + r;
        const float* src;
        if (IS_EDGE) {
            int e = (row < E) ? row : 0;
            int node = half ? eidx[e] : eidx[E + e];   // half0 = i, half1 = j
            src = x + (size_t)node * 128 + part * 64;
        } else {
            int rr = (row < M) ? row : 0;
            src = (half ? second : x) + (size_t)rr * 128 + part * 64;
        }
        uint32_t abase = sb + SM_A + (uint32_t)(r * 528 + half * 256 + part * 128);
#pragma unroll
        for (int jj = 0; jj < 16; ++jj) {
            float4 v = *(const float4*)(src + jj * 4);
            uint32_t h0 = h2bits(__float22half2_rn(make_float2(v.x, v.y)));
            uint32_t h1 = h2bits(__float22half2_rn(make_float2(v.z, v.w)));
            asm volatile("st.shared.v2.b32 [%0], {%1,%2};"
                         :: "r"(abase + jj * 8), "r"(h0), "r"(h1) : "memory");
        }
    }

    // ldmatrix lane base addresses
    const uint32_t aB = sb + SM_A +
        (uint32_t)((wm * 16 + (lane & 15)) * 528 + ((lane >> 4) & 1) * 16);
    const uint32_t bOff = (uint32_t)((wn * 16 + (lane & 7) + ((lane >> 4) & 1) * 8) * 528 +
                                     ((lane >> 3) & 1) * 16);
    const uint32_t hB = sb + SM_H +
        (uint32_t)((wm * 16 + (lane & 15)) * 80 + ((lane >> 4) & 1) * 16);
    uint32_t w2Off[4];
#pragma unroll
    for (int p = 0; p < 4; ++p)
        w2Off[p] = (uint32_t)((wn * 64 + p * 16 + (lane & 7) + ((lane >> 4) & 1) * 8) * 80 +
                              ((lane >> 3) & 1) * 16);

    float acc2[32];
#pragma unroll
    for (int i = 0; i < 32; ++i) acc2[i] = 0.f;

    const int rsub = lane >> 2;        // 0..7
    const int cc = (lane & 3) * 2;

    for (int c = 0; c < NCHUNK; ++c) {
        asm volatile("cp.async.wait_group 0;");
        __syncthreads();   // chunk-c weights visible; H(c-1) consumed

        // ---- GEMM1: acc1[64 x 32chunk], K=256, D += A*(W1h + W1l) ----
        float acc1[8];
#pragma unroll
        for (int i = 0; i < 8; ++i) acc1[i] = 0.f;
#pragma unroll
        for (int s = 0; s < 16; ++s) {
            uint32_t ah[4], bh[4], bl[4];
            ldm4(aB + s * 32, ah);
            ldm4(sb + SM_W1 + bOff + s * 32, bh);
            ldm4(sb + SM_W1 + W1LO + bOff + s * 32, bl);
            mma_f16(acc1 + 0, ah, bh[0], bh[1]);
            mma_f16(acc1 + 4, ah, bh[2], bh[3]);
            mma_f16(acc1 + 0, ah, bl[0], bl[1]);
            mma_f16(acc1 + 4, ah, bl[2], bl[3]);
        }

        // ---- epilogue: relu(acc1 + b1) -> fp16 H smem ----
#pragma unroll
        for (int nq = 0; nq < 2; ++nq) {
            const float* ac = acc1 + nq * 4;
            int gcol = c * 32 + wn * 16 + nq * 8 + cc;
            float ba = __ldg(b1 + gcol), bb = __ldg(b1 + gcol + 1);
            float v00 = fmaxf(ac[0] + ba, 0.f);
            float v01 = fmaxf(ac[1] + bb, 0.f);
            float v10 = fmaxf(ac[2] + ba, 0.f);
            float v11 = fmaxf(ac[3] + bb, 0.f);
            uint32_t p0 = h2bits(__float22half2_rn(make_float2(v00, v01)));
            uint32_t p1 = h2bits(__float22half2_rn(make_float2(v10, v11)));
            int hcol = wn * 16 + nq * 8 + cc;
            uint32_t a0 = sb + SM_H + (uint32_t)((wm * 16 + rsub) * 80 + hcol * 2);
            asm volatile("st.shared.b32 [%0], %1;" :: "r"(a0), "r"(p0) : "memory");
            asm volatile("st.shared.b32 [%0], %1;" :: "r"(a0 + 8 * 80), "r"(p1) : "memory");
        }
        __syncthreads();   // H visible; W1(c) fully consumed

        if (c + 1 < NCHUNK) prefetch_w1(sb, c + 1, w1h, w1l, tid);  // overlaps GEMM2

        // ---- GEMM2: acc2 += H[64x32] @ (W2h+W2l)[32x128] ----
#pragma unroll
        for (int s = 0; s < 2; ++s) {
            uint32_t hh[4];
            ldm4(hB + s * 32, hh);
#pragma unroll
            for (int p = 0; p < 4; ++p) {
                uint32_t bh[4], bl[4];
                ldm4(sb + SM_W2 + w2Off[p] + s * 32, bh);
                ldm4(sb + SM_W2 + W2LO + w2Off[p] + s * 32, bl);
                float* a0 = acc2 + p * 8;
                mma_f16(a0 + 0, hh, bh[0], bh[1]);
                mma_f16(a0 + 4, hh, bh[2], bh[3]);
                mma_f16(a0 + 0, hh, bl[0], bl[1]);
                mma_f16(a0 + 4, hh, bl[2], bl[3]);
            }
        }
        __syncthreads();   // W2(c) consumed
        if (c + 1 < NCHUNK) prefetch_w2(sb, c + 1, w2h, w2l, tid);
        asm volatile("cp.async.commit_group;");
    }

    // ---- final epilogue: out = acc2 + b2 ----
    {
        int e0 = rowbase + wm * 16 + rsub;
        int e1 = e0 + 8;
        int tgt0 = 0, tgt1 = 0;
        if (IS_EDGE) {
            tgt0 = (e0 < E) ? eidx[E + e0] : 0;
            tgt1 = (e1 < E) ? eidx[E + e1] : 0;
        }
#pragma unroll
        for (int p = 0; p < 4; ++p) {
#pragma unroll
            for (int t = 0; t < 2; ++t) {
                const float* ac = acc2 + p * 8 + t * 4;
                int col = wn * 64 + p * 16 + t * 8 + cc;
                float ba = __ldg(b2 + col), bb = __ldg(b2 + col + 1);
                float v00 = ac[0] + ba, v01 = ac[1] + bb;
                float v10 = ac[2] + ba, v11 = ac[3] + bb;
                if (IS_EDGE) {
                    if (e0 < E) {
                        atomicAdd(out + (size_t)tgt0 * 128 + col, v00);
                        atomicAdd(out + (size_t)tgt0 * 128 + col + 1, v01);
                    }
                    if (e1 < E) {
                        atomicAdd(out + (size_t)tgt1 * 128 + col, v10);
                        atomicAdd(out + (size_t)tgt1 * 128 + col + 1, v11);
                    }
                } else {
                    if (e0 < M) *(float2*)(out + (size_t)e0 * 128 + col) = make_float2(v00, v01);
                    if (e1 < M) *(float2*)(out + (size_t)e1 * 128 + col) = make_float2(v10, v11);
                }
            }
        }
    }
}

extern "C" void kernel_launch(void* const* d_in, const int* in_sizes, int n_in,
                              void* d_out, int out_size) {
    const float* x   = (const float*)d_in[0];
    const int* eidx  = (const int*)d_in[2];   // JAX demotes int64 -> int32
    const float* W1m = (const float*)d_in[3];
    const float* b1m = (const float*)d_in[4];
    const float* W2m = (const float*)d_in[5];
    const float* b2m = (const float*)d_in[6];
    const float* W1u = (const float*)d_in[7];
    const float* b1u = (const float*)d_in[8];
    const float* W2u = (const float*)d_in[9];
    const float* b2u = (const float*)d_in[10];
    float* out = (float*)d_out;

    int N = in_sizes[0] / 128;
    int E = in_sizes[2] / 2;

    float* agg; cudaGetSymbolAddress((void**)&agg, g_agg);
    __half *w1mh, *w1ml, *w2mh, *w2ml, *w1uh, *w1ul, *w2uh, *w2ul;
    cudaGetSymbolAddress((void**)&w1mh, g_w1m_hi);
    cudaGetSymbolAddress((void**)&w1ml, g_w1m_lo);
    cudaGetSymbolAddress((void**)&w2mh, g_w2m_hi);
    cudaGetSymbolAddress((void**)&w2ml, g_w2m_lo);
    cudaGetSymbolAddress((void**)&w1uh, g_w1u_hi);
    cudaGetSymbolAddress((void**)&w1ul, g_w1u_lo);
    cudaGetSymbolAddress((void**)&w2uh, g_w2u_hi);
    cudaGetSymbolAddress((void**)&w2ul, g_w2u_lo);

    cudaFuncSetAttribute((const void*)mlp_mma<true>,
                         cudaFuncAttributeMaxDynamicSharedMemorySize, SM_TOTAL);
    cudaFuncSetAttribute((const void*)mlp_mma<false>,
                         cudaFuncAttributeMaxDynamicSharedMemorySize, SM_TOTAL);

    prep_all2<<<7786, NT>>>(W1m, W2m, W1u, W2u, agg);

    mlp_mma<true><<<(E + ROWS - 1) / ROWS, NT, SM_TOTAL>>>(
        x, x, eidx, w1mh, w1ml, w2mh, w2ml, b1m, b2m, agg, E, E);

    mlp_mma<false><<<(N + ROWS - 1) / ROWS, NT, SM_TOTAL>>>(
        x, agg, nullptr, w1uh, w1ul, w2uh, w2ul, b1u, b2u, out, N, 0);
}

// round 10
// speedup vs baseline: 2.0725x; 2.0725x over previous
#include <cuda_runtime.h>
#include <cuda_fp16.h>
#include <cstdint>

#define NT 256
#define ROWS 192
#define NCHUNK 8
// smem byte offsets
#define SM_A    0         // 192 rows x 264 fp16 (stride 528B) = 101376
#define SM_W1   101376    // hi 64n x 264k = 33792
#define SM_W2   135168    // hi 128n x 72k (stride 144B) = 18432
#define SM_H    153600    // 192 x 72 fp16 (stride 144B) = 27648
#define SM_TOTAL 181248

__device__ float g_agg[50000 * 128];
// weight images: fp16 hi only, chunk-contiguous
__device__ __align__(16) __half g_w1m[8 * 64 * 264];
__device__ __align__(16) __half g_w2m[8 * 128 * 72];
__device__ __align__(16) __half g_w1u[8 * 64 * 264];
__device__ __align__(16) __half g_w2u[8 * 128 * 72];

__device__ __forceinline__ uint32_t smem_u32(const void* p) {
    uint32_t a;
    asm("{ .reg .u64 t; cvta.to.shared.u64 t, %1; cvt.u32.u64 %0, t; }" : "=r"(a) : "l"(p));
    return a;
}
__device__ __forceinline__ void ldm4(uint32_t addr, uint32_t* r) {
    asm volatile("ldmatrix.sync.aligned.m8n8.x4.shared.b16 {%0,%1,%2,%3}, [%4];"
                 : "=r"(r[0]), "=r"(r[1]), "=r"(r[2]), "=r"(r[3]) : "r"(addr));
}
__device__ __forceinline__ void mma_f16(float* c, const uint32_t* a,
                                        uint32_t b0, uint32_t b1) {
    asm volatile(
        "mma.sync.aligned.m16n8k16.row.col.f32.f16.f16.f32 "
        "{%0,%1,%2,%3}, {%4,%5,%6,%7}, {%8,%9}, {%0,%1,%2,%3};"
        : "+f"(c[0]), "+f"(c[1]), "+f"(c[2]), "+f"(c[3])
        : "r"(a[0]), "r"(a[1]), "r"(a[2]), "r"(a[3]), "r"(b0), "r"(b1));
}
__device__ __forceinline__ void cp16(uint32_t dst, const void* src) {
    asm volatile("cp.async.cg.shared.global [%0], [%1], 16;" :: "r"(dst), "l"(src));
}
__device__ __forceinline__ uint32_t h2bits(__half2 v) {
    return *reinterpret_cast<uint32_t*>(&v);
}

// ---- merged prep: zero agg + 4 hi-only weight images ----
// blocks: zero [0,6250) | w1m [6250,6762) | w2m [6762,7018) | w1u [7018,7530) | w2u [7530,7786)
__global__ void prep_all(const float* __restrict__ W1m, const float* __restrict__ W2m,
                         const float* __restrict__ W1u, const float* __restrict__ W2u,
                         float* __restrict__ agg) {
    int b = blockIdx.x, tid = threadIdx.x;
    if (b < 6250) {
        ((float4*)agg)[b * NT + tid] = make_float4(0.f, 0.f, 0.f, 0.f);
    } else if (b < 6762 || (b >= 7018 && b < 7530)) {   // W1 [256k x 512n] -> [8 c(n64)][64n][264k]
        bool msg = (b < 6762);
        const float* W = msg ? W1m : W1u;
        __half* hi = msg ? g_w1m : g_w1u;
        int idx = (b - (msg ? 6250 : 7018)) * NT + tid;
        int k = idx >> 9, n = idx & 511;
        hi[(n >> 6) * 16896 + (n & 63) * 264 + k] = __float2half_rn(W[idx]);
    } else {                                            // W2 [512k x 128n] -> [8 c(k64)][128n][72k]
        bool msg = (b < 7018);
        const float* W = msg ? W2m : W2u;
        __half* hi = msg ? g_w2m : g_w2u;
        int idx = (b - (msg ? 6762 : 7530)) * NT + tid;
        int k = idx >> 7, n = idx & 127;
        hi[(k >> 6) * 9216 + n * 72 + (k & 63)] = __float2half_rn(W[idx]);
    }
}

__device__ __forceinline__ void prefetch_w1(uint32_t sb, int c,
                                            const __half* w1, int tid) {
    const char* s = ((const char*)w1) + c * 33792;
#pragma unroll
    for (int j = 0; j < 9; ++j) {
        int idx = tid + j * NT;
        if (idx < 2112) cp16(sb + SM_W1 + idx * 16, s + idx * 16);
    }
    asm volatile("cp.async.commit_group;");
}
__device__ __forceinline__ void prefetch_w2(uint32_t sb, int c,
                                            const __half* w2, int tid) {
    const char* s = ((const char*)w2) + c * 18432;
#pragma unroll
    for (int j = 0; j < 5; ++j) {
        int idx = tid + j * NT;
        if (idx < 1152) cp16(sb + SM_W2 + idx * 16, s + idx * 16);
    }
    asm volatile("cp.async.commit_group;");
}

// Fused 2-layer MLP, 192 rows/CTA, single-term fp16 mma.sync, R7 split-prefetch
// pipeline. Warps: 4m(48 rows) x 2n.
template <bool IS_EDGE>
__global__ __launch_bounds__(NT, 1)
void mlp_mma(const float* __restrict__ x, const float* __restrict__ second,
             const int* __restrict__ eidx,
             const __half* __restrict__ w1, const __half* __restrict__ w2,
             const float* __restrict__ b1, const float* __restrict__ b2,
             float* __restrict__ out, int M, int E) {
    extern __shared__ __align__(16) unsigned char smem[];
    const uint32_t sb = smem_u32(smem);
    const int tid = threadIdx.x;
    const int lane = tid & 31;
    const int wid = tid >> 5;
    const int wm = wid & 3, wn = wid >> 2;
    const int rowbase = blockIdx.x * ROWS;

    prefetch_w1(sb, 0, w1, tid);
    prefetch_w2(sb, 0, w2, tid);

    // ---- gather A = [feat_i(128) | feat_j(128)] -> fp16 smem ----
    for (int idx = tid; idx < ROWS * 2; idx += NT) {
        int r = idx >> 1, half = idx & 1;
        int row = rowbase + r;
        const float* src;
        if (IS_EDGE) {
            int e = (row < E) ? row : 0;
            int node = half ? eidx[e] : eidx[E + e];   // half0 = i, half1 = j
            src = x + (size_t)node * 128;
        } else {
            int rr = (row < M) ? row : 0;
            src = (half ? second : x) + (size_t)rr * 128;
        }
        uint32_t abase = sb + SM_A + (uint32_t)(r * 528 + half * 256);
#pragma unroll
        for (int jj = 0; jj < 32; ++jj) {
            float4 v = *(const float4*)(src + jj * 4);
            uint32_t h0 = h2bits(__float22half2_rn(make_float2(v.x, v.y)));
            uint32_t h1 = h2bits(__float22half2_rn(make_float2(v.z, v.w)));
            asm volatile("st.shared.v2.b32 [%0], {%1,%2};"
                         :: "r"(abase + jj * 8), "r"(h0), "r"(h1) : "memory");
        }
    }

    // ldmatrix base addresses (3 m-frags per warp)
    uint32_t aB[3], hB[3];
#pragma unroll
    for (int mf = 0; mf < 3; ++mf) {
        aB[mf] = sb + SM_A +
            (uint32_t)((wm * 48 + mf * 16 + (lane & 15)) * 528 + ((lane >> 4) & 1) * 16);
        hB[mf] = sb + SM_H +
            (uint32_t)((wm * 48 + mf * 16 + (lane & 15)) * 144 + ((lane >> 4) & 1) * 16);
    }
    const uint32_t bB0 = sb + SM_W1 +
        (uint32_t)((wn * 32 + (lane & 7) + ((lane >> 4) & 1) * 8) * 528 +
                   ((lane >> 3) & 1) * 16);
    const uint32_t bB1 = bB0 + 16 * 528;
    uint32_t w2B[4];
#pragma unroll
    for (int p = 0; p < 4; ++p)
        w2B[p] = sb + SM_W2 +
            (uint32_t)((wn * 64 + p * 16 + (lane & 7) + ((lane >> 4) & 1) * 8) * 144 +
                       ((lane >> 3) & 1) * 16);

    float acc2[96];
#pragma unroll
    for (int i = 0; i < 96; ++i) acc2[i] = 0.f;

    const int rsub = lane >> 2;        // 0..7
    const int cc = (lane & 3) * 2;

    for (int c = 0; c < NCHUNK; ++c) {
        asm volatile("cp.async.wait_group 1;");   // W1(c) ready
        __syncthreads();

        // ---- GEMM1: acc1[192 x 64chunk], K=256, single term ----
        float acc1[48];
#pragma unroll
        for (int i = 0; i < 48; ++i) acc1[i] = 0.f;
#pragma unroll
        for (int s = 0; s < 16; ++s) {
            uint32_t a0[4], a1[4], a2[4], b0[4], b1r[4];
            ldm4(aB[0] + s * 32, a0);
            ldm4(aB[1] + s * 32, a1);
            ldm4(aB[2] + s * 32, a2);
            ldm4(bB0 + s * 32, b0);
            ldm4(bB1 + s * 32, b1r);
            mma_f16(acc1 + 0,  a0, b0[0], b0[1]);
            mma_f16(acc1 + 4,  a0, b0[2], b0[3]);
            mma_f16(acc1 + 8,  a0, b1r[0], b1r[1]);
            mma_f16(acc1 + 12, a0, b1r[2], b1r[3]);
            mma_f16(acc1 + 16, a1, b0[0], b0[1]);
            mma_f16(acc1 + 20, a1, b0[2], b0[3]);
            mma_f16(acc1 + 24, a1, b1r[0], b1r[1]);
            mma_f16(acc1 + 28, a1, b1r[2], b1r[3]);
            mma_f16(acc1 + 32, a2, b0[0], b0[1]);
            mma_f16(acc1 + 36, a2, b0[2], b0[3]);
            mma_f16(acc1 + 40, a2, b1r[0], b1r[1]);
            mma_f16(acc1 + 44, a2, b1r[2], b1r[3]);
        }

        // ---- epilogue: relu(acc1 + b1) -> fp16 H smem ----
#pragma unroll
        for (int mf = 0; mf < 3; ++mf) {
#pragma unroll
            for (int nq = 0; nq < 4; ++nq) {
                const float* ac = acc1 + mf * 16 + nq * 4;
                int gcol = c * 64 + wn * 32 + nq * 8 + cc;
                float ba = __ldg(b1 + gcol), bb = __ldg(b1 + gcol + 1);
                float v00 = fmaxf(ac[0] + ba, 0.f);
                float v01 = fmaxf(ac[1] + bb, 0.f);
                float v10 = fmaxf(ac[2] + ba, 0.f);
                float v11 = fmaxf(ac[3] + bb, 0.f);
                uint32_t p0 = h2bits(__float22half2_rn(make_float2(v00, v01)));
                uint32_t p1 = h2bits(__float22half2_rn(make_float2(v10, v11)));
                int hcol = wn * 32 + nq * 8 + cc;
                int r0 = wm * 48 + mf * 16 + rsub;
                uint32_t a0 = sb + SM_H + (uint32_t)(r0 * 144 + hcol * 2);
                asm volatile("st.shared.b32 [%0], %1;" :: "r"(a0), "r"(p0) : "memory");
                asm volatile("st.shared.b32 [%0], %1;" :: "r"(a0 + 8 * 144), "r"(p1) : "memory");
            }
        }
        __syncthreads();   // H visible; W1 slab free

        if (c + 1 < NCHUNK) {
            prefetch_w1(sb, c + 1, w1, tid);
            asm volatile("cp.async.wait_group 1;");   // W2(c) ready
        } else {
            asm volatile("cp.async.wait_group 0;");
        }
        __syncthreads();

        // ---- GEMM2: acc2 += H[192x64] @ W2[64x128], single term ----
#pragma unroll
        for (int s = 0; s < 4; ++s) {
            uint32_t h0[4], h1[4], h2[4];
            ldm4(hB[0] + s * 32, h0);
            ldm4(hB[1] + s * 32, h1);
            ldm4(hB[2] + s * 32, h2);
#pragma unroll
            for (int p = 0; p < 4; ++p) {
                uint32_t bw[4];
                ldm4(w2B[p] + s * 32, bw);
                mma_f16(acc2 + p * 8 + 0,  h0, bw[0], bw[1]);
                mma_f16(acc2 + p * 8 + 4,  h0, bw[2], bw[3]);
                mma_f16(acc2 + 32 + p * 8 + 0, h1, bw[0], bw[1]);
                mma_f16(acc2 + 32 + p * 8 + 4, h1, bw[2], bw[3]);
                mma_f16(acc2 + 64 + p * 8 + 0, h2, bw[0], bw[1]);
                mma_f16(acc2 + 64 + p * 8 + 4, h2, bw[2], bw[3]);
            }
        }
        __syncthreads();   // W2 slab free
        if (c + 1 < NCHUNK) prefetch_w2(sb, c + 1, w2, tid);
    }

    // ---- final epilogue: out = acc2 + b2 ----
#pragma unroll
    for (int mf = 0; mf < 3; ++mf) {
        int e0 = rowbase + wm * 48 + mf * 16 + rsub;
        int e1 = e0 + 8;
        int tgt0 = 0, tgt1 = 0;
        if (IS_EDGE) {
            tgt0 = (e0 < E) ? eidx[E + e0] : 0;
            tgt1 = (e1 < E) ? eidx[E + e1] : 0;
        }
#pragma unroll
        for (int p = 0; p < 4; ++p) {
#pragma unroll
            for (int t = 0; t < 2; ++t) {
                const float* ac = acc2 + mf * 32 + p * 8 + t * 4;
                int col = wn * 64 + p * 16 + t * 8 + cc;
                float ba = __ldg(b2 + col), bb = __ldg(b2 + col + 1);
                float v00 = ac[0] + ba, v01 = ac[1] + bb;
                float v10 = ac[2] + ba, v11 = ac[3] + bb;
                if (IS_EDGE) {
                    if (e0 < E) {
                        atomicAdd(out + (size_t)tgt0 * 128 + col, v00);
                        atomicAdd(out + (size_t)tgt0 * 128 + col + 1, v01);
                    }
                    if (e1 < E) {
                        atomicAdd(out + (size_t)tgt1 * 128 + col, v10);
                        atomicAdd(out + (size_t)tgt1 * 128 + col + 1, v11);
                    }
                } else {
                    if (e0 < M) *(float2*)(out + (size_t)e0 * 128 + col) = make_float2(v00, v01);
                    if (e1 < M) *(float2*)(out + (size_t)e1 * 128 + col) = make_float2(v10, v11);
                }
            }
        }
    }
}

extern "C" void kernel_launch(void* const* d_in, const int* in_sizes, int n_in,
                              void* d_out, int out_size) {
    const float* x   = (const float*)d_in[0];
    const int* eidx  = (const int*)d_in[2];   // JAX demotes int64 -> int32
    const float* W1m = (const float*)d_in[3];
    const float* b1m = (const float*)d_in[4];
    const float* W2m = (const float*)d_in[5];
    const float* b2m = (const float*)d_in[6];
    const float* W1u = (const float*)d_in[7];
    const float* b1u = (const float*)d_in[8];
    const float* W2u = (const float*)d_in[9];
    const float* b2u = (const float*)d_in[10];
    float* out = (float*)d_out;

    int N = in_sizes[0] / 128;
    int E = in_sizes[2] / 2;

    float* agg; cudaGetSymbolAddress((void**)&agg, g_agg);
    __half *w1m, *w2m, *w1u, *w2u;
    cudaGetSymbolAddress((void**)&w1m, g_w1m);
    cudaGetSymbolAddress((void**)&w2m, g_w2m);
    cudaGetSymbolAddress((void**)&w1u, g_w1u);
    cudaGetSymbolAddress((void**)&w2u, g_w2u);

    cudaFuncSetAttribute((const void*)mlp_mma<true>,
                         cudaFuncAttributeMaxDynamicSharedMemorySize, SM_TOTAL);
    cudaFuncSetAttribute((const void*)mlp_mma<false>,
                         cudaFuncAttributeMaxDynamicSharedMemorySize, SM_TOTAL);

    prep_all<<<7786, NT>>>(W1m, W2m, W1u, W2u, agg);

    mlp_mma<true><<<(E + ROWS - 1) / ROWS, NT, SM_TOTAL>>>(
        x, x, eidx, w1m, w2m, b1m, b2m, agg, E, E);

    mlp_mma<false><<<(N + ROWS - 1) / ROWS, NT, SM_TOTAL>>>(
        x, agg, nullptr, w1u, w2u, b1u, b2u, out, N, 0);
}

// round 11
// speedup vs baseline: 2.0846x; 1.0058x over previous
#include <cuda_runtime.h>
#include <cuda_fp16.h>
#include <cstdint>

#define NT 256
#define ROWS 192
#define NCHUNK 8
// smem byte offsets
#define SM_A    0         // 192 rows x 264 fp16 (stride 528B) = 101376
#define SM_W1   101376    // hi 64n x 264k = 33792
#define SM_W2   135168    // hi 128n x 72k (stride 144B) = 18432
#define SM_H    153600    // 192 x 72 fp16 (stride 144B) = 27648
#define SM_TOTAL 181248

__device__ float g_agg[50000 * 128];
// weight images: fp16 hi only, chunk-contiguous
__device__ __align__(16) __half g_w1m[8 * 64 * 264];
__device__ __align__(16) __half g_w2m[8 * 128 * 72];
__device__ __align__(16) __half g_w1u[8 * 64 * 264];
__device__ __align__(16) __half g_w2u[8 * 128 * 72];

__device__ __forceinline__ uint32_t smem_u32(const void* p) {
    uint32_t a;
    asm("{ .reg .u64 t; cvta.to.shared.u64 t, %1; cvt.u32.u64 %0, t; }" : "=r"(a) : "l"(p));
    return a;
}
__device__ __forceinline__ void ldm4(uint32_t addr, uint32_t* r) {
    asm volatile("ldmatrix.sync.aligned.m8n8.x4.shared.b16 {%0,%1,%2,%3}, [%4];"
                 : "=r"(r[0]), "=r"(r[1]), "=r"(r[2]), "=r"(r[3]) : "r"(addr));
}
__device__ __forceinline__ void mma_f16(float* c, const uint32_t* a,
                                        uint32_t b0, uint32_t b1) {
    asm volatile(
        "mma.sync.aligned.m16n8k16.row.col.f32.f16.f16.f32 "
        "{%0,%1,%2,%3}, {%4,%5,%6,%7}, {%8,%9}, {%0,%1,%2,%3};"
        : "+f"(c[0]), "+f"(c[1]), "+f"(c[2]), "+f"(c[3])
        : "r"(a[0]), "r"(a[1]), "r"(a[2]), "r"(a[3]), "r"(b0), "r"(b1));
}
__device__ __forceinline__ void cp16(uint32_t dst, const void* src) {
    asm volatile("cp.async.cg.shared.global [%0], [%1], 16;" :: "r"(dst), "l"(src));
}
__device__ __forceinline__ uint32_t h2bits(__half2 v) {
    return *reinterpret_cast<uint32_t*>(&v);
}
// vectorized no-return global reduction (sm_90+)
__device__ __forceinline__ void red_v2(float* p, float a, float b) {
    asm volatile("red.global.add.v2.f32 [%0], {%1,%2};"
                 :: "l"(p), "f"(a), "f"(b) : "memory");
}

// ---- merged prep: zero agg + 4 hi-only weight images ----
// blocks: zero [0,6250) | w1m [6250,6762) | w2m [6762,7018) | w1u [7018,7530) | w2u [7530,7786)
__global__ void prep_all(const float* __restrict__ W1m, const float* __restrict__ W2m,
                         const float* __restrict__ W1u, const float* __restrict__ W2u,
                         float* __restrict__ agg) {
    int b = blockIdx.x, tid = threadIdx.x;
    if (b < 6250) {
        ((float4*)agg)[b * NT + tid] = make_float4(0.f, 0.f, 0.f, 0.f);
    } else if (b < 6762 || (b >= 7018 && b < 7530)) {   // W1 [256k x 512n] -> [8 c(n64)][64n][264k]
        bool msg = (b < 6762);
        const float* W = msg ? W1m : W1u;
        __half* hi = msg ? g_w1m : g_w1u;
        int idx = (b - (msg ? 6250 : 7018)) * NT + tid;
        int k = idx >> 9, n = idx & 511;
        hi[(n >> 6) * 16896 + (n & 63) * 264 + k] = __float2half_rn(W[idx]);
    } else {                                            // W2 [512k x 128n] -> [8 c(k64)][128n][72k]
        bool msg = (b < 7018);
        const float* W = msg ? W2m : W2u;
        __half* hi = msg ? g_w2m : g_w2u;
        int idx = (b - (msg ? 6762 : 7530)) * NT + tid;
        int k = idx >> 7, n = idx & 127;
        hi[(k >> 6) * 9216 + n * 72 + (k & 63)] = __float2half_rn(W[idx]);
    }
}

__device__ __forceinline__ void prefetch_w1(uint32_t sb, int c,
                                            const __half* w1, int tid) {
    const char* s = ((const char*)w1) + c * 33792;
#pragma unroll
    for (int j = 0; j < 9; ++j) {
        int idx = tid + j * NT;
        if (idx < 2112) cp16(sb + SM_W1 + idx * 16, s + idx * 16);
    }
    asm volatile("cp.async.commit_group;");
}
__device__ __forceinline__ void prefetch_w2(uint32_t sb, int c,
                                            const __half* w2, int tid) {
    const char* s = ((const char*)w2) + c * 18432;
#pragma unroll
    for (int j = 0; j < 5; ++j) {
        int idx = tid + j * NT;
        if (idx < 1152) cp16(sb + SM_W2 + idx * 16, s + idx * 16);
    }
    asm volatile("cp.async.commit_group;");
}

// Fused 2-layer MLP, 192 rows/CTA, single-term fp16 mma.sync, split-prefetch
// pipeline, v2 vectorized scatter reductions. Warps: 4m(48 rows) x 2n.
template <bool IS_EDGE>
__global__ __launch_bounds__(NT, 1)
void mlp_mma(const float* __restrict__ x, const float* __restrict__ second,
             const int* __restrict__ eidx,
             const __half* __restrict__ w1, const __half* __restrict__ w2,
             const float* __restrict__ b1, const float* __restrict__ b2,
             float* __restrict__ out, int M, int E) {
    extern __shared__ __align__(16) unsigned char smem[];
    const uint32_t sb = smem_u32(smem);
    const int tid = threadIdx.x;
    const int lane = tid & 31;
    const int wid = tid >> 5;
    const int wm = wid & 3, wn = wid >> 2;
    const int rowbase = blockIdx.x * ROWS;

    prefetch_w1(sb, 0, w1, tid);
    prefetch_w2(sb, 0, w2, tid);

    // ---- gather A = [feat_i(128) | feat_j(128)] -> fp16 smem ----
    for (int idx = tid; idx < ROWS * 2; idx += NT) {
        int r = idx >> 1, half = idx & 1;
        int row = rowbase + r;
        const float* src;
        if (IS_EDGE) {
            int e = (row < E) ? row : 0;
            int node = half ? eidx[e] : eidx[E + e];   // half0 = i, half1 = j
            src = x + (size_t)node * 128;
        } else {
            int rr = (row < M) ? row : 0;
            src = (half ? second : x) + (size_t)rr * 128;
        }
        uint32_t abase = sb + SM_A + (uint32_t)(r * 528 + half * 256);
#pragma unroll
        for (int jj = 0; jj < 32; ++jj) {
            float4 v = *(const float4*)(src + jj * 4);
            uint32_t h0 = h2bits(__float22half2_rn(make_float2(v.x, v.y)));
            uint32_t h1 = h2bits(__float22half2_rn(make_float2(v.z, v.w)));
            asm volatile("st.shared.v2.b32 [%0], {%1,%2};"
                         :: "r"(abase + jj * 8), "r"(h0), "r"(h1) : "memory");
        }
    }

    // ldmatrix base addresses (3 m-frags per warp)
    uint32_t aB[3], hB[3];
#pragma unroll
    for (int mf = 0; mf < 3; ++mf) {
        aB[mf] = sb + SM_A +
            (uint32_t)((wm * 48 + mf * 16 + (lane & 15)) * 528 + ((lane >> 4) & 1) * 16);
        hB[mf] = sb + SM_H +
            (uint32_t)((wm * 48 + mf * 16 + (lane & 15)) * 144 + ((lane >> 4) & 1) * 16);
    }
    const uint32_t bB0 = sb + SM_W1 +
        (uint32_t)((wn * 32 + (lane & 7) + ((lane >> 4) & 1) * 8) * 528 +
                   ((lane >> 3) & 1) * 16);
    const uint32_t bB1 = bB0 + 16 * 528;
    uint32_t w2B[4];
#pragma unroll
    for (int p = 0; p < 4; ++p)
        w2B[p] = sb + SM_W2 +
            (uint32_t)((wn * 64 + p * 16 + (lane & 7) + ((lane >> 4) & 1) * 8) * 144 +
                       ((lane >> 3) & 1) * 16);

    float acc2[96];
#pragma unroll
    for (int i = 0; i < 96; ++i) acc2[i] = 0.f;

    const int rsub = lane >> 2;        // 0..7
    const int cc = (lane & 3) * 2;

    for (int c = 0; c < NCHUNK; ++c) {
        asm volatile("cp.async.wait_group 1;");   // W1(c) ready
        __syncthreads();

        // ---- GEMM1: acc1[192 x 64chunk], K=256, single term ----
        float acc1[48];
#pragma unroll
        for (int i = 0; i < 48; ++i) acc1[i] = 0.f;
#pragma unroll
        for (int s = 0; s < 16; ++s) {
            uint32_t a0[4], a1[4], a2[4], b0[4], b1r[4];
            ldm4(aB[0] + s * 32, a0);
            ldm4(aB[1] + s * 32, a1);
            ldm4(aB[2] + s * 32, a2);
            ldm4(bB0 + s * 32, b0);
            ldm4(bB1 + s * 32, b1r);
            mma_f16(acc1 + 0,  a0, b0[0], b0[1]);
            mma_f16(acc1 + 4,  a0, b0[2], b0[3]);
            mma_f16(acc1 + 8,  a0, b1r[0], b1r[1]);
            mma_f16(acc1 + 12, a0, b1r[2], b1r[3]);
            mma_f16(acc1 + 16, a1, b0[0], b0[1]);
            mma_f16(acc1 + 20, a1, b0[2], b0[3]);
            mma_f16(acc1 + 24, a1, b1r[0], b1r[1]);
            mma_f16(acc1 + 28, a1, b1r[2], b1r[3]);
            mma_f16(acc1 + 32, a2, b0[0], b0[1]);
            mma_f16(acc1 + 36, a2, b0[2], b0[3]);
            mma_f16(acc1 + 40, a2, b1r[0], b1r[1]);
            mma_f16(acc1 + 44, a2, b1r[2], b1r[3]);
        }

        // ---- epilogue: relu(acc1 + b1) -> fp16 H smem ----
#pragma unroll
        for (int mf = 0; mf < 3; ++mf) {
#pragma unroll
            for (int nq = 0; nq < 4; ++nq) {
                const float* ac = acc1 + mf * 16 + nq * 4;
                int gcol = c * 64 + wn * 32 + nq * 8 + cc;
                float ba = __ldg(b1 + gcol), bb = __ldg(b1 + gcol + 1);
                float v00 = fmaxf(ac[0] + ba, 0.f);
                float v01 = fmaxf(ac[1] + bb, 0.f);
                float v10 = fmaxf(ac[2] + ba, 0.f);
                float v11 = fmaxf(ac[3] + bb, 0.f);
                uint32_t p0 = h2bits(__float22half2_rn(make_float2(v00, v01)));
                uint32_t p1 = h2bits(__float22half2_rn(make_float2(v10, v11)));
                int hcol = wn * 32 + nq * 8 + cc;
                int r0 = wm * 48 + mf * 16 + rsub;
                uint32_t a0 = sb + SM_H + (uint32_t)(r0 * 144 + hcol * 2);
                asm volatile("st.shared.b32 [%0], %1;" :: "r"(a0), "r"(p0) : "memory");
                asm volatile("st.shared.b32 [%0], %1;" :: "r"(a0 + 8 * 144), "r"(p1) : "memory");
            }
        }
        __syncthreads();   // H visible; W1 slab free

        if (c + 1 < NCHUNK) {
            prefetch_w1(sb, c + 1, w1, tid);
            asm volatile("cp.async.wait_group 1;");   // W2(c) ready
        } else {
            asm volatile("cp.async.wait_group 0;");
        }
        __syncthreads();

        // ---- GEMM2: acc2 += H[192x64] @ W2[64x128], single term ----
#pragma unroll
        for (int s = 0; s < 4; ++s) {
            uint32_t h0[4], h1[4], h2[4];
            ldm4(hB[0] + s * 32, h0);
            ldm4(hB[1] + s * 32, h1);
            ldm4(hB[2] + s * 32, h2);
#pragma unroll
            for (int p = 0; p < 4; ++p) {
                uint32_t bw[4];
                ldm4(w2B[p] + s * 32, bw);
                mma_f16(acc2 + p * 8 + 0,  h0, bw[0], bw[1]);
                mma_f16(acc2 + p * 8 + 4,  h0, bw[2], bw[3]);
                mma_f16(acc2 + 32 + p * 8 + 0, h1, bw[0], bw[1]);
                mma_f16(acc2 + 32 + p * 8 + 4, h1, bw[2], bw[3]);
                mma_f16(acc2 + 64 + p * 8 + 0, h2, bw[0], bw[1]);
                mma_f16(acc2 + 64 + p * 8 + 4, h2, bw[2], bw[3]);
            }
        }
        __syncthreads();   // W2 slab free
        if (c + 1 < NCHUNK) prefetch_w2(sb, c + 1, w2, tid);
    }

    // ---- final epilogue: out = acc2 + b2 (v2 reductions / stores) ----
#pragma unroll
    for (int mf = 0; mf < 3; ++mf) {
        int e0 = rowbase + wm * 48 + mf * 16 + rsub;
        int e1 = e0 + 8;
        int tgt0 = 0, tgt1 = 0;
        if (IS_EDGE) {
            tgt0 = (e0 < E) ? eidx[E + e0] : 0;
            tgt1 = (e1 < E) ? eidx[E + e1] : 0;
        }
#pragma unroll
        for (int p = 0; p < 4; ++p) {
#pragma unroll
            for (int t = 0; t < 2; ++t) {
                const float* ac = acc2 + mf * 32 + p * 8 + t * 4;
                int col = wn * 64 + p * 16 + t * 8 + cc;
                float ba = __ldg(b2 + col), bb = __ldg(b2 + col + 1);
                float v00 = ac[0] + ba, v01 = ac[1] + bb;
                float v10 = ac[2] + ba, v11 = ac[3] + bb;
                if (IS_EDGE) {
                    if (e0 < E) red_v2(out + (size_t)tgt0 * 128 + col, v00, v01);
                    if (e1 < E) red_v2(out + (size_t)tgt1 * 128 + col, v10, v11);
                } else {
                    if (e0 < M) *(float2*)(out + (size_t)e0 * 128 + col) = make_float2(v00, v01);
                    if (e1 < M) *(float2*)(out + (size_t)e1 * 128 + col) = make_float2(v10, v11);
                }
            }
        }
    }
}

extern "C" void kernel_launch(void* const* d_in, const int* in_sizes, int n_in,
                              void* d_out, int out_size) {
    const float* x   = (const float*)d_in[0];
    const int* eidx  = (const int*)d_in[2];   // JAX demotes int64 -> int32
    const float* W1m = (const float*)d_in[3];
    const float* b1m = (const float*)d_in[4];
    const float* W2m = (const float*)d_in[5];
    const float* b2m = (const float*)d_in[6];
    const float* W1u = (const float*)d_in[7];
    const float* b1u = (const float*)d_in[8];
    const float* W2u = (const float*)d_in[9];
    const float* b2u = (const float*)d_in[10];
    float* out = (float*)d_out;

    int N = in_sizes[0] / 128;
    int E = in_sizes[2] / 2;

    float* agg; cudaGetSymbolAddress((void**)&agg, g_agg);
    __half *w1m, *w2m, *w1u, *w2u;
    cudaGetSymbolAddress((void**)&w1m, g_w1m);
    cudaGetSymbolAddress((void**)&w2m, g_w2m);
    cudaGetSymbolAddress((void**)&w1u, g_w1u);
    cudaGetSymbolAddress((void**)&w2u, g_w2u);

    cudaFuncSetAttribute((const void*)mlp_mma<true>,
                         cudaFuncAttributeMaxDynamicSharedMemorySize, SM_TOTAL);
    cudaFuncSetAttribute((const void*)mlp_mma<false>,
                         cudaFuncAttributeMaxDynamicSharedMemorySize, SM_TOTAL);

    prep_all<<<7786, NT>>>(W1m, W2m, W1u, W2u, agg);

    mlp_mma<true><<<(E + ROWS - 1) / ROWS, NT, SM_TOTAL>>>(
        x, x, eidx, w1m, w2m, b1m, b2m, agg, E, E);

    mlp_mma<false><<<(N + ROWS - 1) / ROWS, NT, SM_TOTAL>>>(
        x, agg, nullptr, w1u, w2u, b1u, b2u, out, N, 0);
}